// round 7
// baseline (speedup 1.0000x reference)
#include <cuda_runtime.h>
#include <cstdint>

// GeneralizedGraphDiffusion: out = prelu((sum_k theta_k*T_k * a) @ x) @ W^T + b
// N=8192, D=128, K=4.
// R7: mma.sync tf32; BM 64->32, grid 256, __launch_bounds__(256,2) -> 2 CTAs/SM,
// all 148 SMs covered, barrier convoys overlap across CTAs.

#define NN 8192
#define DDIM 128
#define BM 32
#define BK 32
#define NT (NN / BK)         // 256 tiles
#define TPB 256

// smem word offsets (floats): A = 32*36 = 1152 each, B = 4096 each
#define AB0 0
#define AB1 1152
#define BB0 2304
#define BB1 6400
#define SMEM_WORDS 10496     // 41984 bytes (static, <48KB)
#define HS_STRIDE 132

__device__ __forceinline__ uint32_t tf32r(float f) {
    uint32_t r;
    asm("cvt.rna.tf32.f32 %0, %1;" : "=r"(r) : "f"(f));
    return r;
}
__device__ __forceinline__ void mma8(float* c, uint32_t a0, uint32_t a1,
                                     uint32_t a2, uint32_t a3,
                                     uint32_t b0, uint32_t b1) {
    asm volatile(
        "mma.sync.aligned.m16n8k8.row.col.f32.tf32.tf32.f32 "
        "{%0,%1,%2,%3}, {%4,%5,%6,%7}, {%8,%9}, {%0,%1,%2,%3};"
        : "+f"(c[0]), "+f"(c[1]), "+f"(c[2]), "+f"(c[3])
        : "r"(a0), "r"(a1), "r"(a2), "r"(a3), "r"(b0), "r"(b1));
}

__global__ __launch_bounds__(TPB, 2)
void ggd_kernel(const float* __restrict__ theta, const float* __restrict__ T,
                const float* __restrict__ x, const float* __restrict__ a,
                const float* __restrict__ alpha, const float* __restrict__ W,
                const float* __restrict__ bias, float* __restrict__ out) {
    __shared__ __align__(16) float sm[SMEM_WORDS];
    const int tid = threadIdx.x;
    const int wid = tid >> 5, lane = tid & 31;
    const int g = lane >> 2, tig = lane & 3;     // groupID, threadID_in_group
    const int wc = wid;                          // warp owns 32 rows x 16 cols
    const int i0 = blockIdx.x * BM;

    const float th0 = __ldg(theta), th1 = __ldg(theta + 1),
                th2 = __ldg(theta + 2), th3 = __ldg(theta + 3);
    const size_t slice = (size_t)NN * NN;

    // ---- A staging: 256 quads (row 0..31, c4 0..7), exactly 1 per thread ----
    const int rowA = tid >> 3, cA = (tid & 7) * 4;
    const size_t rbA = (size_t)(i0 + rowA) * NN + cA;
    const int stA = rowA * 36 + cA;

    // ---- B staging: col bn = tid&127, khalf = tid>>7 (16 k's each) ----
    const int bn = tid & 127, kh = tid >> 7;
    const int bnf = bn >> 3, bg = bn & 7;

    float4 pT[4], pa;
    float px[16];

#define LOADR(J0) do {                                                         \
    size_t _o = rbA + (size_t)(J0);                                            \
    pT[0] = *(const float4*)(T + _o);                                          \
    pT[1] = *(const float4*)(T + slice + _o);                                  \
    pT[2] = *(const float4*)(T + 2*slice + _o);                                \
    pT[3] = *(const float4*)(T + 3*slice + _o);                                \
    pa    = *(const float4*)(a + _o);                                          \
    const float* _xp = x + (size_t)((J0) + kh * 16) * DDIM + bn;               \
    _Pragma("unroll") for (int _j = 0; _j < 16; _j++) px[_j] = __ldg(_xp + _j * DDIM); \
} while (0)

#define STOREB(Abase, Bbase) do {                                              \
    {                                                                          \
        float4 t0 = pT[0], t1 = pT[1], t2 = pT[2], t3 = pT[3], av = pa;        \
        uint32_t qx = tf32r((th0*t0.x + th1*t1.x + th2*t2.x + th3*t3.x) * av.x); \
        uint32_t qy = tf32r((th0*t0.y + th1*t1.y + th2*t2.y + th3*t3.y) * av.y); \
        uint32_t qz = tf32r((th0*t0.z + th1*t1.z + th2*t2.z + th3*t3.z) * av.z); \
        uint32_t qw = tf32r((th0*t0.w + th1*t1.w + th2*t2.w + th3*t3.w) * av.w); \
        uint32_t* _d = (uint32_t*)(sm + (Abase) + stA);                        \
        asm volatile("st.shared.v4.b32 [%0], {%1,%2,%3,%4};" ::                \
            "l"(_d), "r"(qx), "r"(qy), "r"(qz), "r"(qw) : "memory");           \
    }                                                                          \
    _Pragma("unroll") for (int _ksl = 0; _ksl < 2; _ksl++) {                   \
        int _ks = kh * 2 + _ksl;                                               \
        uint32_t v0 = tf32r(px[_ksl*8 + 0]), v1 = tf32r(px[_ksl*8 + 4]);       \
        uint32_t v2 = tf32r(px[_ksl*8 + 1]), v3 = tf32r(px[_ksl*8 + 5]);       \
        uint32_t v4 = tf32r(px[_ksl*8 + 2]), v5 = tf32r(px[_ksl*8 + 6]);       \
        uint32_t v6 = tf32r(px[_ksl*8 + 3]), v7 = tf32r(px[_ksl*8 + 7]);       \
        uint32_t* _d = (uint32_t*)(sm + (Bbase) + bnf*256 + _ks*64 + bg*8);    \
        asm volatile("st.shared.v4.b32 [%0], {%1,%2,%3,%4};" ::                \
            "l"(_d), "r"(v0), "r"(v1), "r"(v2), "r"(v3) : "memory");           \
        asm volatile("st.shared.v4.b32 [%0], {%1,%2,%3,%4};" ::                \
            "l"(_d + 4), "r"(v4), "r"(v5), "r"(v6), "r"(v7) : "memory");       \
    }                                                                          \
} while (0)

    float acc[2][2][4];
#pragma unroll
    for (int mi = 0; mi < 2; mi++)
#pragma unroll
        for (int nf = 0; nf < 2; nf++)
#pragma unroll
            for (int e = 0; e < 4; e++) acc[mi][nf][e] = 0.f;

    LOADR(0);
    for (int t = 0; t < NT; t++) {
        const int Abase = (t & 1) ? AB1 : AB0;
        const int Bbase = (t & 1) ? BB1 : BB0;
        STOREB(Abase, Bbase);
        __syncthreads();
        if (t + 1 < NT) LOADR((t + 1) * BK);

        const uint32_t* As = (const uint32_t*)(sm + Abase);
        const uint32_t* Bs = (const uint32_t*)(sm + Bbase);
#pragma unroll
        for (int ks = 0; ks < 4; ks++) {
            uint32_t af[2][4];
#pragma unroll
            for (int mi = 0; mi < 2; mi++) {
                const uint32_t* ap = As + (mi*16 + g) * 36 + ks*8 + tig;
                af[mi][0] = ap[0];
                af[mi][1] = ap[8 * 36];
                af[mi][2] = ap[4];
                af[mi][3] = ap[8 * 36 + 4];
            }
#pragma unroll
            for (int nfl = 0; nfl < 2; nfl++) {
                const int nf = wc * 2 + nfl;
                uint2 bb = *(const uint2*)(Bs + ((nf*4 + ks)*32 + lane)*2);
#pragma unroll
                for (int mi = 0; mi < 2; mi++)
                    mma8(acc[mi][nfl], af[mi][0], af[mi][1], af[mi][2], af[mi][3],
                         bb.x, bb.y);
            }
        }
    }

    // ---- epilogue: acc -> hs (raw h), then prelu + projection ----
    __syncthreads();
    float* hs = sm;   // [32][HS_STRIDE] = 4224 words
#pragma unroll
    for (int mi = 0; mi < 2; mi++)
#pragma unroll
        for (int nfl = 0; nfl < 2; nfl++) {
            const int col = (wc*2 + nfl)*8 + tig*2;
            const int r0 = mi*16 + g;
            *(float2*)(hs + r0 * HS_STRIDE + col) =
                make_float2(acc[mi][nfl][0], acc[mi][nfl][1]);
            *(float2*)(hs + (r0 + 8) * HS_STRIDE + col) =
                make_float2(acc[mi][nfl][2], acc[mi][nfl][3]);
        }
    __syncthreads();

    const int tx = tid & 15, ty = tid >> 4;
    const int tx8 = tx * 8, ty2 = ty * 2;
    float oa[2][8];
#pragma unroll
    for (int m = 0; m < 2; m++)
#pragma unroll
        for (int u = 0; u < 8; u++) oa[m][u] = 0.f;

    for (int c4 = 0; c4 < 32; c4++) {
        float4 al = __ldg((const float4*)(alpha + c4 * 4));
        float4 wv[8];
#pragma unroll
        for (int u = 0; u < 8; u++)
            wv[u] = __ldg((const float4*)(W + (size_t)(tx8 + u) * DDIM + c4 * 4));
#pragma unroll
        for (int m = 0; m < 2; m++) {
            float4 hv = *(const float4*)(hs + (ty2 + m) * HS_STRIDE + c4 * 4);
            hv.x = hv.x > 0.f ? hv.x : al.x * hv.x;
            hv.y = hv.y > 0.f ? hv.y : al.y * hv.y;
            hv.z = hv.z > 0.f ? hv.z : al.z * hv.z;
            hv.w = hv.w > 0.f ? hv.w : al.w * hv.w;
#pragma unroll
            for (int u = 0; u < 8; u++)
                oa[m][u] += hv.x * wv[u].x + hv.y * wv[u].y +
                            hv.z * wv[u].z + hv.w * wv[u].w;
        }
    }

    float4 b0 = __ldg((const float4*)(bias + tx8));
    float4 b1 = __ldg((const float4*)(bias + tx8 + 4));
#pragma unroll
    for (int m = 0; m < 2; m++) {
        size_t go = (size_t)(i0 + ty2 + m) * DDIM;
        *(float4*)(out + go + tx8) = make_float4(oa[m][0] + b0.x, oa[m][1] + b0.y,
                                                 oa[m][2] + b0.z, oa[m][3] + b0.w);
        *(float4*)(out + go + tx8 + 4) = make_float4(oa[m][4] + b1.x, oa[m][5] + b1.y,
                                                     oa[m][6] + b1.z, oa[m][7] + b1.w);
    }
}

extern "C" void kernel_launch(void* const* d_in, const int* in_sizes, int n_in,
                              void* d_out, int out_size) {
    const float* theta = (const float*)d_in[0];
    const float* T     = (const float*)d_in[1];
    const float* x     = (const float*)d_in[2];
    const float* a     = (const float*)d_in[3];
    const float* alpha = (const float*)d_in[4];
    const float* W     = (const float*)d_in[5];
    const float* bias  = (const float*)d_in[6];
    (void)in_sizes; (void)n_in; (void)out_size;

    ggd_kernel<<<NN / BM, TPB>>>(theta, T, x, a, alpha, W, bias, (float*)d_out);
}